// round 9
// baseline (speedup 1.0000x reference)
#include <cuda_runtime.h>

#define GRIDA 592
#define GRIDB 1480
#define TPB   256
#define MAXB  1048576

__device__ float4 g_hn[MAXB];               // layer-norm outputs (A -> B)
__device__ float  g_partials[GRIDA * 16];   // per-block [8 sums, 8 sumsq]
// g_final: [0:6) m, [6:12) c2, [12:36) w2p (W2 pre-scaled by sc), [36:39) bp
__device__ float  g_final[39];
__device__ unsigned g_done = 0;             // self-resetting ticket (replay-safe)

__device__ __forceinline__ float ex2f(float x) {
    float y; asm("ex2.approx.ftz.f32 %0, %1;" : "=f"(y) : "f"(x)); return y;
}
__device__ __forceinline__ float sin_fast(float x) {
    float y; asm("sin.approx.ftz.f32 %0, %1;" : "=f"(y) : "f"(x)); return y;
}

// =======================  PASS A  =======================
__global__ __launch_bounds__(TPB, 4)
void passA(const float* __restrict__ xg,
           const float* __restrict__ W1, const float* __restrict__ b1,
           const float* __restrict__ gam, const float* __restrict__ bet,
           const float* __restrict__ mIn, const float* __restrict__ th,
           const float* __restrict__ g2, const float* __restrict__ bt2,
           const float* __restrict__ W2, const float* __restrict__ b2,
           int n, int rpb)
{
    __shared__ float w1s[32];          // W1 (smem, broadcast LDS in loop)
    __shared__ float sprm[24];         // b1 0..2, gam 3..5, bet 6..8, m 9..14, c2 15..20
    __shared__ float stage[8 * 352];   // 8 warps x 32 rows x 11 floats (conflict-free pad)
    __shared__ float t2s[8];
    __shared__ int   sflag;

    const int tid = threadIdx.x, bid = blockIdx.x;
    const int wid = tid >> 5, lane = tid & 31;

    if (tid < 30) w1s[tid] = W1[tid];
    else if (tid < 33) sprm[tid - 30] = b1[tid - 30];       // 0..2
    else if (tid < 36) sprm[tid - 30] = gam[tid - 33];      // 3..5
    else if (tid < 39) sprm[tid - 30] = bet[tid - 36];      // 6..8
    else if (tid < 45) sprm[tid - 30] = mIn[tid - 39];      // 9..14
    else if (tid < 51) { const float v = th[tid - 45];      // 15..20
                         sprm[tid - 30] = -1.4426950408889634f / (2.0f * v * v); }
    __syncthreads();

    // small params -> registers (21 floats)
    float bb1[3], gm[3], bt[3], mv[6], c2[6];
#pragma unroll
    for (int i = 0; i < 3; i++) { bb1[i] = sprm[i]; gm[i] = sprm[3 + i]; bt[i] = sprm[6 + i]; }
#pragma unroll
    for (int i = 0; i < 6; i++) { mv[i] = sprm[9 + i]; c2[i] = sprm[15 + i]; }

    const int row0 = bid * rpb;
    const int rEnd = min(row0 + rpb, n);
    float* buf = stage + wid * 352;
    const float C2 = 0.99999f * 0.99999f;
    const int iters = (rpb + TPB - 1) / TPB;

    float acc[16];
#pragma unroll
    for (int i = 0; i < 16; i++) acc[i] = 0.f;

    for (int k = 0; k < iters; k++) {
        const int warpBase = row0 + k * TPB + wid * 32;
        if (warpBase < rEnd) {
            const float* src = xg + (size_t)warpBase * 10;
            const int lim = (rEnd - warpBase) * 10;
#pragma unroll
            for (int j = 0; j < 10; j++) {
                const int idx = j * 32 + lane;
                if (idx < lim) buf[(idx / 10) * 11 + (idx % 10)] = src[idx];
            }
        }
        __syncwarp();
        const int r = warpBase + lane;
        if (r < rEnd) {
            float xv[10];
#pragma unroll
            for (int j = 0; j < 10; j++) xv[j] = buf[lane * 11 + j];

            float h[3];
#pragma unroll
            for (int q = 0; q < 3; q++) {
                float a = bb1[q];
#pragma unroll
                for (int c = 0; c < 10; c++) a = fmaf(xv[c], w1s[q * 10 + c], a);
                h[q] = a;
            }
            const float mu = (h[0] + h[1] + h[2]) * (1.0f / 3.0f);
            const float d0 = h[0] - mu, d1 = h[1] - mu, d2 = h[2] - mu;
            const float var = (d0 * d0 + d1 * d1 + d2 * d2) * (1.0f / 3.0f);
            const float rn = rsqrtf(var + 1e-5f);
            const float hn0 = fmaf(d0 * rn, gm[0], bt[0]);
            const float hn1 = fmaf(d1 * rn, gm[1], bt[1]);
            const float hn2 = fmaf(d2 * rn, gm[2], bt[2]);
            g_hn[r] = make_float4(hn0, hn1, hn2, 0.f);

            float p[6];
#pragma unroll
            for (int kk = 0; kk < 6; kk++) {
                const float hq = (kk < 2) ? hn0 : (kk < 4) ? hn1 : hn2;
                const float a = hq - mv[kk];
                const float f = ex2f(a * a * c2[kk]);
                const float pv = fminf(f + 1e-16f, C2);
                p[kk] = (kk < 2) ? pv : (1.0f - pv);
            }
            const float w00 = p[2] * p[4], w01 = p[2] * p[5];
            const float w10 = p[3] * p[4], w11 = p[3] * p[5];
            float o[8];
            o[0] = p[0] * w00; o[1] = p[0] * w01; o[2] = p[0] * w10; o[3] = p[0] * w11;
            o[4] = p[1] * w00; o[5] = p[1] * w01; o[6] = p[1] * w10; o[7] = p[1] * w11;
#pragma unroll
            for (int c = 0; c < 8; c++) {
                acc[c] += o[c];
                acc[8 + c] = fmaf(o[c], o[c], acc[8 + c]);
            }
        }
        __syncwarp();
    }

    // deterministic block reduction -> g_partials
    __syncthreads();
    float* red = stage;
#pragma unroll
    for (int kk = 0; kk < 16; kk++) {
        float v = acc[kk];
#pragma unroll
        for (int off = 16; off; off >>= 1)
            v += __shfl_down_sync(0xffffffffu, v, off);
        if (lane == 0) red[wid * 16 + kk] = v;
    }
    __syncthreads();
    if (tid < 16) {
        float s = 0.f;
#pragma unroll
        for (int w = 0; w < 8; w++) s += red[w * 16 + tid];
        g_partials[bid * 16 + tid] = s;
    }

    // ---- last block folds partials -> full passB param block in g_final ----
    if (tid == 0) {
        __threadfence();
        const unsigned t = atomicAdd(&g_done, 1u);
        sflag = (t == GRIDA - 1u) ? 1 : 0;
    }
    __syncthreads();
    if (sflag) {
        float* red2 = stage + 512;
        {
            const int met = tid & 15, ch = tid >> 4;
            float s = 0.f;
            for (int b = ch; b < GRIDA; b += 16)
                s += __ldcg(&g_partials[b * 16 + met]);
            red2[tid] = s;
        }
        __syncthreads();
        if (tid < 16) {
            float s = 0.f;
#pragma unroll
            for (int w = 0; w < 16; w++) s += red2[w * 16 + tid];
            stage[tid] = s;      // totals: [0:8) sums, [8:16) sumsq
        }
        __syncthreads();
        if (tid < 8) {
            const float invB = 1.0f / (float)n;
            const float muv = stage[tid] * invB;
            const float msq = stage[8 + tid] * invB;
            const float var = msq - muv * muv;
            const float sc = g2[tid] * rsqrtf(var + 1e-5f);
            stage[16 + tid] = sc;
            t2s[tid] = bt2[tid] - muv * sc;
        }
        __syncthreads();
        if (tid < 6)  g_final[tid] = mv[tid];
        else if (tid < 12) g_final[tid] = c2[tid - 6];
        else if (tid < 36) {           // w2p[i*8+c] = W2[i*8+c] * sc[c]
            const int i = (tid - 12) >> 3, c = (tid - 12) & 7;
            g_final[tid] = W2[i * 8 + c] * stage[16 + c];
        } else if (tid < 39) {          // bp[i] = b2[i] + sum_c t2[c]*W2[i*8+c]
            const int i = tid - 36;
            float a = b2[i];
#pragma unroll
            for (int c = 0; c < 8; c++) a = fmaf(t2s[c], W2[i * 8 + c], a);
            g_final[tid] = a;
        }
        if (tid == 0) g_done = 0;    // reset for next replay
    }
}

// =======================  PASS B  =======================
__global__ __launch_bounds__(TPB, 4)
void passB(float* __restrict__ outg, int n)
{
    __shared__ float sf[40];
    const int tid = threadIdx.x, bid = blockIdx.x;

    if (tid < 39) sf[tid] = g_final[tid];
    __syncthreads();

    float mv[6], c2[6], w2p[24], bp[3];
#pragma unroll
    for (int i = 0; i < 6; i++) { mv[i] = sf[i]; c2[i] = sf[6 + i]; }
#pragma unroll
    for (int i = 0; i < 24; i++) w2p[i] = sf[12 + i];
#pragma unroll
    for (int i = 0; i < 3; i++) bp[i] = sf[36 + i];

    const float C2 = 0.99999f * 0.99999f;
    const int NTB = GRIDB * TPB;

    for (int r = bid * TPB + tid; r < n; r += NTB) {
        const float4 hv = g_hn[r];
        float p[6];
#pragma unroll
        for (int kk = 0; kk < 6; kk++) {
            const float hq = (kk < 2) ? hv.x : (kk < 4) ? hv.y : hv.z;
            const float a = hq - mv[kk];
            const float f = ex2f(a * a * c2[kk]);
            const float pv = fminf(f + 1e-16f, C2);
            p[kk] = (kk < 2) ? pv : (1.0f - pv);
        }
        const float w00 = p[2] * p[4], w01 = p[2] * p[5];
        const float w10 = p[3] * p[4], w11 = p[3] * p[5];
        float o[8];
        o[0] = p[0] * w00; o[1] = p[0] * w01; o[2] = p[0] * w10; o[3] = p[0] * w11;
        o[4] = p[1] * w00; o[5] = p[1] * w01; o[6] = p[1] * w10; o[7] = p[1] * w11;
        float lg[3];
#pragma unroll
        for (int i = 0; i < 3; i++) {
            float a = bp[i];
#pragma unroll
            for (int c = 0; c < 8; c++) a = fmaf(o[c], w2p[i * 8 + c], a);
            lg[i] = a;
        }
        const float sg0 = sin_fast(lg[0] * 0.5f);
        const float sg1 = sin_fast(lg[1] * 0.5f);
        const float sg2 = sin_fast(lg[2] * 0.5f);
        const float pq0 = sg0 * sg0, pq1 = sg1 * sg1, pq2 = sg2 * sg2;
        const float cq0 = 1.f - pq0, cq1 = 1.f - pq1, cq2 = 1.f - pq2;
        const float tt = cq1 * cq2;
        float* dst = outg + (size_t)r * 3;
        dst[0] = cq0 * tt;
        dst[1] = pq0 * tt;
        dst[2] = cq0 * (pq1 * cq2);
    }
}

extern "C" void kernel_launch(void* const* d_in, const int* in_sizes, int n_in,
                              void* d_out, int out_size)
{
    const float* x = (const float*)d_in[0];
    const int n = in_sizes[0] / 10;
    const int rpb = (n + GRIDA - 1) / GRIDA;

    passA<<<GRIDA, TPB>>>(x,
        (const float*)d_in[1], (const float*)d_in[2], (const float*)d_in[3],
        (const float*)d_in[4], (const float*)d_in[5], (const float*)d_in[6],
        (const float*)d_in[7], (const float*)d_in[8], (const float*)d_in[9],
        (const float*)d_in[10], n, rpb);

    passB<<<GRIDB, TPB>>>((float*)d_out, n);
}

// round 10
// speedup vs baseline: 1.1455x; 1.1455x over previous
#include <cuda_runtime.h>

#define GRIDA 592
#define GRIDB 1480
#define TPB   256
#define MAXB  1048576

__device__ float4 g_hn[MAXB];               // layer-norm outputs (A -> B)
__device__ float  g_partials[GRIDA * 16];   // per-block [8 sums, 8 sumsq]
// g_final: [0:6) m, [6:12) c2, [12:36) w2p (W2 pre-scaled by sc), [36:39) bp
__device__ float  g_final[39];
__device__ unsigned g_done = 0;             // self-resetting ticket (replay-safe)

__device__ __forceinline__ float ex2f(float x) {
    float y; asm("ex2.approx.ftz.f32 %0, %1;" : "=f"(y) : "f"(x)); return y;
}
__device__ __forceinline__ float sin_fast(float x) {
    float y; asm("sin.approx.ftz.f32 %0, %1;" : "=f"(y) : "f"(x)); return y;
}

// =======================  PASS A  =======================
// (256,2): 128-reg budget so ALL params (incl. W1) hoist from smem into registers.
__global__ __launch_bounds__(TPB, 2)
void passA(const float* __restrict__ xg,
           const float* __restrict__ W1, const float* __restrict__ b1,
           const float* __restrict__ gam, const float* __restrict__ bet,
           const float* __restrict__ mIn, const float* __restrict__ th,
           const float* __restrict__ g2, const float* __restrict__ bt2,
           const float* __restrict__ W2, const float* __restrict__ b2,
           int n)
{
    __shared__ float sprm[52];     // W1 0..29, b1 30..32, gam 33..35, bet 36..38, m 39..44, c2 45..50
    __shared__ float red[128];     // 8 warps x 16
    __shared__ float red2[256];
    __shared__ float tot[24];      // totals + sc
    __shared__ float t2s[8];
    __shared__ int   sflag;

    const int tid = threadIdx.x, bid = blockIdx.x;
    const int wid = tid >> 5, lane = tid & 31;

    if      (tid < 30) sprm[tid] = W1[tid];
    else if (tid < 33) sprm[tid] = b1[tid - 30];
    else if (tid < 36) sprm[tid] = gam[tid - 33];
    else if (tid < 39) sprm[tid] = bet[tid - 36];
    else if (tid < 45) sprm[tid] = mIn[tid - 39];
    else if (tid < 51) { const float v = th[tid - 45];
                         sprm[tid] = -1.4426950408889634f / (2.0f * v * v); }
    __syncthreads();

    // hoist ALL params into registers (no smem access in mainloop)
    float w1[30], bb1[3], gm[3], bt[3], mv[6], c2[6];
#pragma unroll
    for (int i = 0; i < 30; i++) w1[i] = sprm[i];
#pragma unroll
    for (int i = 0; i < 3; i++) { bb1[i] = sprm[30 + i]; gm[i] = sprm[33 + i]; bt[i] = sprm[36 + i]; }
#pragma unroll
    for (int i = 0; i < 6; i++) { mv[i] = sprm[39 + i]; c2[i] = sprm[45 + i]; }

    const float C2 = 0.99999f * 0.99999f;
    const int NTOT = GRIDA * TPB;

    float acc[16];
#pragma unroll
    for (int i = 0; i < 16; i++) acc[i] = 0.f;

    for (int r = bid * TPB + tid; r < n; r += NTOT) {
        const float2* xp = (const float2*)(xg + (size_t)r * 10);
        const float2 v0 = xp[0], v1 = xp[1], v2 = xp[2], v3 = xp[3], v4 = xp[4];
        const float xv[10] = {v0.x, v0.y, v1.x, v1.y, v2.x,
                              v2.y, v3.x, v3.y, v4.x, v4.y};
        float h[3];
#pragma unroll
        for (int q = 0; q < 3; q++) {
            float a = bb1[q];
#pragma unroll
            for (int c = 0; c < 10; c++) a = fmaf(xv[c], w1[q * 10 + c], a);
            h[q] = a;
        }
        const float mu = (h[0] + h[1] + h[2]) * (1.0f / 3.0f);
        const float d0 = h[0] - mu, d1 = h[1] - mu, d2 = h[2] - mu;
        const float var = (d0 * d0 + d1 * d1 + d2 * d2) * (1.0f / 3.0f);
        const float rn = rsqrtf(var + 1e-5f);
        const float hn0 = fmaf(d0 * rn, gm[0], bt[0]);
        const float hn1 = fmaf(d1 * rn, gm[1], bt[1]);
        const float hn2 = fmaf(d2 * rn, gm[2], bt[2]);
        g_hn[r] = make_float4(hn0, hn1, hn2, 0.f);

        float p[6];
#pragma unroll
        for (int kk = 0; kk < 6; kk++) {
            const float hq = (kk < 2) ? hn0 : (kk < 4) ? hn1 : hn2;
            const float a = hq - mv[kk];
            const float f = ex2f(a * a * c2[kk]);
            const float pv = fminf(f + 1e-16f, C2);
            p[kk] = (kk < 2) ? pv : (1.0f - pv);
        }
        const float w00 = p[2] * p[4], w01 = p[2] * p[5];
        const float w10 = p[3] * p[4], w11 = p[3] * p[5];
        float o[8];
        o[0] = p[0] * w00; o[1] = p[0] * w01; o[2] = p[0] * w10; o[3] = p[0] * w11;
        o[4] = p[1] * w00; o[5] = p[1] * w01; o[6] = p[1] * w10; o[7] = p[1] * w11;
#pragma unroll
        for (int c = 0; c < 8; c++) {
            acc[c] += o[c];
            acc[8 + c] = fmaf(o[c], o[c], acc[8 + c]);
        }
    }

    // deterministic block reduction -> g_partials
#pragma unroll
    for (int kk = 0; kk < 16; kk++) {
        float v = acc[kk];
#pragma unroll
        for (int off = 16; off; off >>= 1)
            v += __shfl_down_sync(0xffffffffu, v, off);
        if (lane == 0) red[wid * 16 + kk] = v;
    }
    __syncthreads();
    if (tid < 16) {
        float s = 0.f;
#pragma unroll
        for (int w = 0; w < 8; w++) s += red[w * 16 + tid];
        g_partials[bid * 16 + tid] = s;
    }

    // ---- last block folds partials -> full passB param block in g_final ----
    if (tid == 0) {
        __threadfence();
        const unsigned t = atomicAdd(&g_done, 1u);
        sflag = (t == GRIDA - 1u) ? 1 : 0;
    }
    __syncthreads();
    if (sflag) {
        {
            const int met = tid & 15, ch = tid >> 4;
            float s = 0.f;
            for (int b = ch; b < GRIDA; b += 16)
                s += __ldcg(&g_partials[b * 16 + met]);
            red2[tid] = s;
        }
        __syncthreads();
        if (tid < 16) {
            float s = 0.f;
#pragma unroll
            for (int w = 0; w < 16; w++) s += red2[w * 16 + tid];
            tot[tid] = s;            // [0:8) sums, [8:16) sumsq
        }
        __syncthreads();
        if (tid < 8) {
            const float invB = 1.0f / (float)n;
            const float muv = tot[tid] * invB;
            const float msq = tot[8 + tid] * invB;
            const float var = msq - muv * muv;
            const float sc = g2[tid] * rsqrtf(var + 1e-5f);
            tot[16 + tid] = sc;
            t2s[tid] = bt2[tid] - muv * sc;
        }
        __syncthreads();
        if (tid < 6)       g_final[tid] = mv[tid];
        else if (tid < 12) g_final[tid] = c2[tid - 6];
        else if (tid < 36) {            // w2p[i*8+c] = W2[i*8+c] * sc[c]
            const int i = (tid - 12) >> 3, c = (tid - 12) & 7;
            g_final[tid] = W2[i * 8 + c] * tot[16 + c];
        } else if (tid < 39) {          // bp[i] = b2[i] + sum_c t2[c]*W2[i*8+c]
            const int i = tid - 36;
            float a = b2[i];
#pragma unroll
            for (int c = 0; c < 8; c++) a = fmaf(t2s[c], W2[i * 8 + c], a);
            g_final[tid] = a;
        }
        if (tid == 0) g_done = 0;    // reset for next replay
    }
}

// =======================  PASS B  (unchanged from R9, measured 11.5us)  =======================
__global__ __launch_bounds__(TPB, 4)
void passB(float* __restrict__ outg, int n)
{
    __shared__ float sf[40];
    const int tid = threadIdx.x, bid = blockIdx.x;

    if (tid < 39) sf[tid] = g_final[tid];
    __syncthreads();

    float mv[6], c2[6], w2p[24], bp[3];
#pragma unroll
    for (int i = 0; i < 6; i++) { mv[i] = sf[i]; c2[i] = sf[6 + i]; }
#pragma unroll
    for (int i = 0; i < 24; i++) w2p[i] = sf[12 + i];
#pragma unroll
    for (int i = 0; i < 3; i++) bp[i] = sf[36 + i];

    const float C2 = 0.99999f * 0.99999f;
    const int NTB = GRIDB * TPB;

    for (int r = bid * TPB + tid; r < n; r += NTB) {
        const float4 hv = g_hn[r];
        float p[6];
#pragma unroll
        for (int kk = 0; kk < 6; kk++) {
            const float hq = (kk < 2) ? hv.x : (kk < 4) ? hv.y : hv.z;
            const float a = hq - mv[kk];
            const float f = ex2f(a * a * c2[kk]);
            const float pv = fminf(f + 1e-16f, C2);
            p[kk] = (kk < 2) ? pv : (1.0f - pv);
        }
        const float w00 = p[2] * p[4], w01 = p[2] * p[5];
        const float w10 = p[3] * p[4], w11 = p[3] * p[5];
        float o[8];
        o[0] = p[0] * w00; o[1] = p[0] * w01; o[2] = p[0] * w10; o[3] = p[0] * w11;
        o[4] = p[1] * w00; o[5] = p[1] * w01; o[6] = p[1] * w10; o[7] = p[1] * w11;
        float lg[3];
#pragma unroll
        for (int i = 0; i < 3; i++) {
            float a = bp[i];
#pragma unroll
            for (int c = 0; c < 8; c++) a = fmaf(o[c], w2p[i * 8 + c], a);
            lg[i] = a;
        }
        const float sg0 = sin_fast(lg[0] * 0.5f);
        const float sg1 = sin_fast(lg[1] * 0.5f);
        const float sg2 = sin_fast(lg[2] * 0.5f);
        const float pq0 = sg0 * sg0, pq1 = sg1 * sg1, pq2 = sg2 * sg2;
        const float cq0 = 1.f - pq0, cq1 = 1.f - pq1, cq2 = 1.f - pq2;
        const float tt = cq1 * cq2;
        float* dst = outg + (size_t)r * 3;
        dst[0] = cq0 * tt;
        dst[1] = pq0 * tt;
        dst[2] = cq0 * (pq1 * cq2);
    }
}

extern "C" void kernel_launch(void* const* d_in, const int* in_sizes, int n_in,
                              void* d_out, int out_size)
{
    const float* x = (const float*)d_in[0];
    const int n = in_sizes[0] / 10;

    passA<<<GRIDA, TPB>>>(x,
        (const float*)d_in[1], (const float*)d_in[2], (const float*)d_in[3],
        (const float*)d_in[4], (const float*)d_in[5], (const float*)d_in[6],
        (const float*)d_in[7], (const float*)d_in[8], (const float*)d_in[9],
        (const float*)d_in[10], n);

    passB<<<GRIDB, TPB>>>((float*)d_out, n);
}

// round 11
// speedup vs baseline: 1.2267x; 1.0708x over previous
#include <cuda_runtime.h>

#define GRIDA 592
#define GRIDB 888
#define TPB   256
#define MAXB  1048576

__constant__ float cW1[30];                 // W1 via one direct D2D memcpy node

__device__ float4 g_hn[MAXB];               // z = (h-mu)*rsqrt(var+eps), pre-affine (A -> B)
__device__ float  g_partials[GRIDA * 16];   // per-block [8 sums, 8 sumsq]
// g_final: [0:6) m', [6:12) c2', [12:36) w2p (W2 pre-scaled by sc), [36:39) bp
__device__ float  g_final[39];
__device__ unsigned g_done = 0;             // self-resetting ticket (replay-safe)

__device__ __forceinline__ float ex2f(float x) {
    float y; asm("ex2.approx.ftz.f32 %0, %1;" : "=f"(y) : "f"(x)); return y;
}
__device__ __forceinline__ float sin_fast(float x) {
    float y; asm("sin.approx.ftz.f32 %0, %1;" : "=f"(y) : "f"(x)); return y;
}

// =======================  PASS A  =======================
// W1 from cbank (LDCU->UR, zero GPRs). gamma/beta folded into m'/c2'.
__global__ __launch_bounds__(TPB, 4)
void passA(const float* __restrict__ xg,
           const float* __restrict__ b1,
           const float* __restrict__ gam, const float* __restrict__ bet,
           const float* __restrict__ mIn, const float* __restrict__ th,
           const float* __restrict__ g2, const float* __restrict__ bt2,
           const float* __restrict__ W2, const float* __restrict__ b2,
           int n)
{
    __shared__ float sprm[21];     // b1 0..2, gam 3..5, bet 6..8, m 9..14, th 15..20
    __shared__ float red[128];     // 8 warps x 16
    __shared__ float red2[256];
    __shared__ float tot[24];      // totals + sc
    __shared__ float t2s[8];
    __shared__ int   sflag;

    const int tid = threadIdx.x, bid = blockIdx.x;
    const int wid = tid >> 5, lane = tid & 31;

    if      (tid < 3)  sprm[tid] = b1[tid];
    else if (tid < 6)  sprm[tid] = gam[tid - 3];
    else if (tid < 9)  sprm[tid] = bet[tid - 6];
    else if (tid < 15) sprm[tid] = mIn[tid - 9];
    else if (tid < 21) sprm[tid] = th[tid - 15];
    __syncthreads();

    // fold LN affine into membership constants:
    //   m'[k]  = (m[k] - bet[q]) / gam[q]
    //   c2'[k] = -log2(e)/(2 th^2) * gam[q]^2
    float bb1[3], mv[6], c2[6];
#pragma unroll
    for (int i = 0; i < 3; i++) bb1[i] = sprm[i];
#pragma unroll
    for (int k = 0; k < 6; k++) {
        const int q = k >> 1;
        const float g = sprm[3 + q], b = sprm[6 + q];
        const float t = sprm[15 + k];
        mv[k] = (sprm[9 + k] - b) / g;
        c2[k] = (-1.4426950408889634f / (2.0f * t * t)) * g * g;
    }

    const float C2 = 0.99999f * 0.99999f;
    const int NTOT = GRIDA * TPB;

    float acc[16];
#pragma unroll
    for (int i = 0; i < 16; i++) acc[i] = 0.f;

    for (int r = bid * TPB + tid; r < n; r += NTOT) {
        const float2* xp = (const float2*)(xg + (size_t)r * 10);
        const float2 v0 = xp[0], v1 = xp[1], v2 = xp[2], v3 = xp[3], v4 = xp[4];
        const float xv[10] = {v0.x, v0.y, v1.x, v1.y, v2.x,
                              v2.y, v3.x, v3.y, v4.x, v4.y};
        float h[3];
#pragma unroll
        for (int q = 0; q < 3; q++) {
            float a = bb1[q];
#pragma unroll
            for (int c = 0; c < 10; c++) a = fmaf(xv[c], cW1[q * 10 + c], a);
            h[q] = a;
        }
        const float mu = (h[0] + h[1] + h[2]) * (1.0f / 3.0f);
        const float d0 = h[0] - mu, d1 = h[1] - mu, d2 = h[2] - mu;
        const float var = (d0 * d0 + d1 * d1 + d2 * d2) * (1.0f / 3.0f);
        const float rn = rsqrtf(var + 1e-5f);
        const float z0 = d0 * rn, z1 = d1 * rn, z2 = d2 * rn;   // pre-affine LN output
        g_hn[r] = make_float4(z0, z1, z2, 0.f);

        float p[6];
#pragma unroll
        for (int kk = 0; kk < 6; kk++) {
            const float zq = (kk < 2) ? z0 : (kk < 4) ? z1 : z2;
            const float a = zq - mv[kk];
            const float f = ex2f(a * a * c2[kk]);
            const float pv = fminf(f + 1e-16f, C2);
            p[kk] = (kk < 2) ? pv : (1.0f - pv);
        }
        const float w00 = p[2] * p[4], w01 = p[2] * p[5];
        const float w10 = p[3] * p[4], w11 = p[3] * p[5];
        float o[8];
        o[0] = p[0] * w00; o[1] = p[0] * w01; o[2] = p[0] * w10; o[3] = p[0] * w11;
        o[4] = p[1] * w00; o[5] = p[1] * w01; o[6] = p[1] * w10; o[7] = p[1] * w11;
#pragma unroll
        for (int c = 0; c < 8; c++) {
            acc[c] += o[c];
            acc[8 + c] = fmaf(o[c], o[c], acc[8 + c]);
        }
    }

    // deterministic block reduction -> g_partials
#pragma unroll
    for (int kk = 0; kk < 16; kk++) {
        float v = acc[kk];
#pragma unroll
        for (int off = 16; off; off >>= 1)
            v += __shfl_down_sync(0xffffffffu, v, off);
        if (lane == 0) red[wid * 16 + kk] = v;
    }
    __syncthreads();
    if (tid < 16) {
        float s = 0.f;
#pragma unroll
        for (int w = 0; w < 8; w++) s += red[w * 16 + tid];
        g_partials[bid * 16 + tid] = s;
    }

    // ---- last block folds partials -> full passB param block in g_final ----
    if (tid == 0) {
        __threadfence();
        const unsigned t = atomicAdd(&g_done, 1u);
        sflag = (t == GRIDA - 1u) ? 1 : 0;
    }
    __syncthreads();
    if (sflag) {
        {
            const int met = tid & 15, ch = tid >> 4;
            float s = 0.f;
            for (int b = ch; b < GRIDA; b += 16)
                s += __ldcg(&g_partials[b * 16 + met]);
            red2[tid] = s;
        }
        __syncthreads();
        if (tid < 16) {
            float s = 0.f;
#pragma unroll
            for (int w = 0; w < 16; w++) s += red2[w * 16 + tid];
            tot[tid] = s;            // [0:8) sums, [8:16) sumsq
        }
        __syncthreads();
        if (tid < 8) {
            const float invB = 1.0f / (float)n;
            const float muv = tot[tid] * invB;
            const float msq = tot[8 + tid] * invB;
            const float var = msq - muv * muv;
            const float sc = g2[tid] * rsqrtf(var + 1e-5f);
            tot[16 + tid] = sc;
            t2s[tid] = bt2[tid] - muv * sc;
        }
        __syncthreads();
        if (tid < 6)       g_final[tid] = mv[tid];        // transformed m'
        else if (tid < 12) g_final[tid] = c2[tid - 6];    // transformed c2'
        else if (tid < 36) {            // w2p[i*8+c] = W2[i*8+c] * sc[c]
            const int i = (tid - 12) >> 3, c = (tid - 12) & 7;
            g_final[tid] = W2[i * 8 + c] * tot[16 + c];
        } else if (tid < 39) {          // bp[i] = b2[i] + sum_c t2[c]*W2[i*8+c]
            const int i = tid - 36;
            float a = b2[i];
#pragma unroll
            for (int c = 0; c < 8; c++) a = fmaf(t2s[c], W2[i * 8 + c], a);
            g_final[tid] = a;
        }
        if (tid == 0) g_done = 0;    // reset for next replay
    }
}

// =======================  PASS B  (2-row batched loads for MLP=2)  =======================
__global__ __launch_bounds__(TPB, 3)
void passB(float* __restrict__ outg, int n)
{
    __shared__ float sf[40];
    const int tid = threadIdx.x, bid = blockIdx.x;

    if (tid < 39) sf[tid] = g_final[tid];
    __syncthreads();

    float mv[6], c2[6], w2p[24], bp[3];
#pragma unroll
    for (int i = 0; i < 6; i++) { mv[i] = sf[i]; c2[i] = sf[6 + i]; }
#pragma unroll
    for (int i = 0; i < 24; i++) w2p[i] = sf[12 + i];
#pragma unroll
    for (int i = 0; i < 3; i++) bp[i] = sf[36 + i];

    const float C2 = 0.99999f * 0.99999f;
    const int NTB = GRIDB * TPB;

    for (int base = bid * TPB + tid; base < n; base += 2 * NTB) {
        const int r0 = base, r1 = base + NTB;
        // front-batched independent loads (MLP=2)
        const float4 hv0 = g_hn[r0];
        float4 hv1;
        const bool v1 = r1 < n;
        if (v1) hv1 = g_hn[r1];

#pragma unroll
        for (int rr = 0; rr < 2; rr++) {
            if (rr == 1 && !v1) break;
            const float4 hv = (rr == 0) ? hv0 : hv1;
            const int r = (rr == 0) ? r0 : r1;
            float p[6];
#pragma unroll
            for (int kk = 0; kk < 6; kk++) {
                const float zq = (kk < 2) ? hv.x : (kk < 4) ? hv.y : hv.z;
                const float a = zq - mv[kk];
                const float f = ex2f(a * a * c2[kk]);
                const float pv = fminf(f + 1e-16f, C2);
                p[kk] = (kk < 2) ? pv : (1.0f - pv);
            }
            const float w00 = p[2] * p[4], w01 = p[2] * p[5];
            const float w10 = p[3] * p[4], w11 = p[3] * p[5];
            float o[8];
            o[0] = p[0] * w00; o[1] = p[0] * w01; o[2] = p[0] * w10; o[3] = p[0] * w11;
            o[4] = p[1] * w00; o[5] = p[1] * w01; o[6] = p[1] * w10; o[7] = p[1] * w11;
            float lg[3];
#pragma unroll
            for (int i = 0; i < 3; i++) {
                float a = bp[i];
#pragma unroll
                for (int c = 0; c < 8; c++) a = fmaf(o[c], w2p[i * 8 + c], a);
                lg[i] = a;
            }
            const float sg0 = sin_fast(lg[0] * 0.5f);
            const float sg1 = sin_fast(lg[1] * 0.5f);
            const float sg2 = sin_fast(lg[2] * 0.5f);
            const float pq0 = sg0 * sg0, pq1 = sg1 * sg1, pq2 = sg2 * sg2;
            const float cq0 = 1.f - pq0, cq1 = 1.f - pq1, cq2 = 1.f - pq2;
            const float tt = cq1 * cq2;
            float* dst = outg + (size_t)r * 3;
            dst[0] = cq0 * tt;
            dst[1] = pq0 * tt;
            dst[2] = cq0 * (pq1 * cq2);
        }
    }
}

extern "C" void kernel_launch(void* const* d_in, const int* in_sizes, int n_in,
                              void* d_out, int out_size)
{
    const float* x = (const float*)d_in[0];
    const int n = in_sizes[0] / 10;

    // single memcpy node: W1 -> cbank (LDCU/UR operand path in passA)
    cudaMemcpyToSymbolAsync(cW1, d_in[1], 30 * sizeof(float), 0,
                            cudaMemcpyDeviceToDevice, 0);

    passA<<<GRIDA, TPB>>>(x,
        (const float*)d_in[2], (const float*)d_in[3], (const float*)d_in[4],
        (const float*)d_in[5], (const float*)d_in[6], (const float*)d_in[7],
        (const float*)d_in[8], (const float*)d_in[9], (const float*)d_in[10], n);

    passB<<<GRIDB, TPB>>>((float*)d_out, n);
}